// round 10
// baseline (speedup 1.0000x reference)
#include <cuda_runtime.h>
#include <cuda_fp16.h>
#include <math.h>
#include <stdint.h>

#define NROWS    8192
#define DIM      1024
#define NCLASSES 50257
#define CUT0     4000
#define CUT1     20000
#define MGUARD   20.0f

#define MT  128
#define NT  128
#define BK  64
#define NCH (DIM / BK)            /* 16 k-chunks */
#define RT  (NROWS / MT)          /* 64 row tiles */
#define COLS_PAD 50688

#define YT_HEAD 32
#define YT_T1   125
#define YT_T2   237
#define YTOT    (YT_HEAD + YT_T1 + YT_T2)   /* 394 */

#define STAGE_BYTES 32768         /* A 16KB + B 16KB per stage */
#define NSTAGE 3
#define SM_TOTAL (NSTAGE * STAGE_BYTES)     /* 96KB -> 2 CTAs/SM */

#define SW128(o) ((o) ^ (((o) >> 3) & 0x70))

/* prep kernel block partition */
#define CVTW_BLOCKS (((long)COLS_PAD * DIM / 16 + 255) / 256)   /* 12672 */
#define CVTA_BLOCKS (((long)NROWS * DIM / 16 + 255) / 256)      /* 2048 */
#define CLS_BLOCKS  (NROWS / 256)                               /* 32 */
#define PREP_BLOCKS (CVTW_BLOCKS + CVTA_BLOCKS + CLS_BLOCKS)

// ---------------- device scratch ----------------
__device__ __align__(256) __half g_A16[(size_t)NROWS * DIM];
__device__ __align__(256) __half g_W16[(size_t)COLS_PAD * DIM];
__device__ float g_head[NROWS];
__device__ float g_t1[NROWS];
__device__ float g_t2[NROWS];
__device__ int   g_rows_c1[NROWS];
__device__ int   g_rows_c2[NROWS];
__device__ int   g_cnt[2];

// ---------------- PTX helpers ----------------
__device__ __forceinline__ uint32_t smem_u32(const void* p) {
    uint32_t a;
    asm("{ .reg .u64 t; cvta.to.shared.u64 t, %1; cvt.u32.u64 %0, t; }" : "=r"(a) : "l"(p));
    return a;
}
__device__ __forceinline__ void cp16(uint32_t dst, const void* src) {
    asm volatile("cp.async.cg.shared.global [%0], [%1], 16;" :: "r"(dst), "l"(src) : "memory");
}
__device__ __forceinline__ void cp_commit() {
    asm volatile("cp.async.commit_group;" ::: "memory");
}
template <int N>
__device__ __forceinline__ void cp_wait() {
    asm volatile("cp.async.wait_group %0;" :: "n"(N) : "memory");
}
__device__ __forceinline__ void ldm_x4(uint32_t* r, uint32_t addr) {
    asm volatile("ldmatrix.sync.aligned.m8n8.x4.shared.b16 {%0,%1,%2,%3}, [%4];"
                 : "=r"(r[0]), "=r"(r[1]), "=r"(r[2]), "=r"(r[3]) : "r"(addr));
}
__device__ __forceinline__ void ldm_x4_t(uint32_t* r, uint32_t addr) {
    asm volatile("ldmatrix.sync.aligned.m8n8.x4.trans.shared.b16 {%0,%1,%2,%3}, [%4];"
                 : "=r"(r[0]), "=r"(r[1]), "=r"(r[2]), "=r"(r[3]) : "r"(addr));
}
// fp16-accumulate HMMA: D,C are 2 b32 regs (4 halfs, same element positions
// as the f32 variant's c0..c3)
__device__ __forceinline__ void mma_fp16h(uint32_t* c, const uint32_t* a, const uint32_t* b) {
    asm volatile(
        "mma.sync.aligned.m16n8k16.row.col.f16.f16.f16.f16 "
        "{%0,%1}, {%2,%3,%4,%5}, {%6,%7}, {%0,%1};"
        : "+r"(c[0]), "+r"(c[1])
        : "r"(a[0]), "r"(a[1]), "r"(a[2]), "r"(a[3]), "r"(b[0]), "r"(b[1]));
}

// ---------------- init: zero accumulators + counters + loss ----------------
__global__ void init_kernel(float* out, int out_size) {
    int i = blockIdx.x * blockDim.x + threadIdx.x;
    if (i < NROWS) { g_head[i] = 0.f; g_t1[i] = 0.f; g_t2[i] = 0.f; }
    if (i < 2) g_cnt[i] = 0;
    if (i == 0 && out_size > NROWS) out[NROWS] = 0.f;
}

// ---------------- prep: weight-cvt + input-cvt + classify ----------------
__device__ __forceinline__ uint32_t pack2hf(float a, float b) {
    __half2 t = __floats2half2_rn(a, b);
    return *reinterpret_cast<uint32_t*>(&t);
}
__device__ __forceinline__ void cvt16(const float* __restrict__ src, __half* __restrict__ dst,
                                      long i, long n_src) {
    uint4 o;
    if (i < n_src) {
        float4 v0 = ((const float4*)src)[i / 4];
        float4 v1 = ((const float4*)src)[i / 4 + 1];
        float4 v2 = ((const float4*)src)[i / 4 + 2];
        float4 v3 = ((const float4*)src)[i / 4 + 3];
        uint4 p;
        p.x = pack2hf(v0.x, v0.y); p.y = pack2hf(v0.z, v0.w);
        p.z = pack2hf(v1.x, v1.y); p.w = pack2hf(v1.z, v1.w);
        o = p;
        *((uint4*)(dst + i)) = o;
        p.x = pack2hf(v2.x, v2.y); p.y = pack2hf(v2.z, v2.w);
        p.z = pack2hf(v3.x, v3.y); p.w = pack2hf(v3.z, v3.w);
        *((uint4*)(dst + i + 8)) = p;
    } else {
        o = make_uint4(0, 0, 0, 0);
        *((uint4*)(dst + i)) = o;
        *((uint4*)(dst + i + 8)) = o;
    }
}
__global__ void prep_kernel(const float* __restrict__ input,
                            const float* __restrict__ weight,
                            const int*   __restrict__ target) {
    long bx = blockIdx.x;
    if (bx < CVTW_BLOCKS) {
        long i = (bx * 256 + threadIdx.x) * 16;
        if (i < (long)COLS_PAD * DIM)
            cvt16(weight, g_W16, i, (long)NCLASSES * DIM);
    } else if (bx < CVTW_BLOCKS + CVTA_BLOCKS) {
        long i = ((bx - CVTW_BLOCKS) * 256 + threadIdx.x) * 16;
        if (i < (long)NROWS * DIM)
            cvt16(input, g_A16, i, (long)NROWS * DIM);
    } else {
        int r = (int)(bx - CVTW_BLOCKS - CVTA_BLOCKS) * 256 + threadIdx.x;
        if (r < NROWS) {
            int t = target[r];
            if (t >= CUT1)      { int p = atomicAdd(&g_cnt[1], 1); g_rows_c2[p] = r; }
            else if (t >= CUT0) { int p = atomicAdd(&g_cnt[0], 1); g_rows_c1[p] = r; }
        }
    }
}

// ---------------- fused HMMA exp-sum GEMM (fp16 accumulate) ----------------
__global__ void __launch_bounds__(256, 2)
hmma_fused(const float* __restrict__ bias)
{
    extern __shared__ char smem[];
    const uint32_t sb = smem_u32(smem);
    const int tid = threadIdx.x;
    const int wid = tid >> 5;
    const int lane = tid & 31;

    // ---- region decode ----
    int ty = blockIdx.y;
    int col_lo, col_hi;
    const int* rowlist;
    int cnt;
    float* acc;
    if (ty < YT_HEAD) {
        col_lo = 0; col_hi = CUT0; rowlist = nullptr; cnt = NROWS; acc = g_head;
    } else if (ty < YT_HEAD + YT_T1) {
        ty -= YT_HEAD;
        col_lo = CUT0; col_hi = CUT1; rowlist = g_rows_c1; cnt = g_cnt[0]; acc = g_t1;
    } else {
        ty -= YT_HEAD + YT_T1;
        col_lo = CUT1; col_hi = NCLASSES; rowlist = g_rows_c2; cnt = g_cnt[1]; acc = g_t2;
    }
    const int row0 = blockIdx.x * MT;
    if (row0 >= cnt) return;
    const int col0 = col_lo + ty * NT;

    // ---- cp.async setup ----
    const __half* asrc[4];
    const __half* bsrc[4];
    uint32_t adst[4], bdst[4];
#pragma unroll
    for (int i = 0; i < 4; i++) {
        int c = tid + 256 * i;
        int r = c >> 3;
        int kc = c & 7;
        int rr = row0 + r;
        int grow;
        if (rowlist) grow = rowlist[rr < cnt ? rr : cnt - 1];
        else         grow = rr;
        asrc[i] = g_A16 + (size_t)grow * DIM + kc * 8;
        adst[i] = sb + SW128(r * 128 + kc * 16);
        bsrc[i] = g_W16 + (size_t)(col0 + r) * DIM + kc * 8;
        bdst[i] = sb + 16384 + SW128(r * 128 + kc * 16);
    }

    // prologue: stages 0,1
#pragma unroll
    for (int s = 0; s < 2; s++) {
        const uint32_t st = s * STAGE_BYTES;
#pragma unroll
        for (int i = 0; i < 4; i++) {
            cp16(adst[i] + st, asrc[i] + s * BK);
            cp16(bdst[i] + st, bsrc[i] + s * BK);
        }
        cp_commit();
    }

    // ---- warp fragment addressing ----
    const int wm = wid & 1;
    const int wn = wid >> 1;
    const int arow = wm * 64 + (lane & 15);
    const uint32_t a_xor = (arow & 7) << 4;
    const uint32_t a_kext = (lane >> 4) << 4;
    const int ln = lane & 7, sel = lane >> 3;
    const int brow = wn * 32 + ln + ((sel >> 1) << 3);
    const uint32_t b_xor = (uint32_t)ln << 4;
    const uint32_t b_kext = (sel & 1) << 4;

    // fp16 accumulators: [mi][ni][2] packed h2 (c0c1, c2c3)
    uint32_t hfr[4][4][2];
#pragma unroll
    for (int mi = 0; mi < 4; mi++)
#pragma unroll
        for (int ni = 0; ni < 4; ni++) { hfr[mi][ni][0] = 0u; hfr[mi][ni][1] = 0u; }

    int stg_c = 0;
    int stg_p = 2;
    for (int ch = 0; ch < NCH; ch++) {
        if (ch < NCH - 1) cp_wait<1>(); else cp_wait<0>();
        __syncthreads();

        if (ch + 2 < NCH) {
            const uint32_t st = stg_p * STAGE_BYTES;
            const int kof = (ch + 2) * BK;
#pragma unroll
            for (int i = 0; i < 4; i++) {
                cp16(adst[i] + st, asrc[i] + kof);
                cp16(bdst[i] + st, bsrc[i] + kof);
            }
            cp_commit();
        }
        if (++stg_p == NSTAGE) stg_p = 0;

        const uint32_t st = stg_c * STAGE_BYTES;
        if (++stg_c == NSTAGE) stg_c = 0;
        const uint32_t Ab = sb + st + (uint32_t)arow * 128;
        const uint32_t Bb = sb + st + 16384 + (uint32_t)brow * 128;

#pragma unroll
        for (int kk = 0; kk < 4; kk++) {
            uint32_t a[4][4], b[2][4];
            const uint32_t kbA = (kk * 32 + a_kext) ^ a_xor;
            const uint32_t kbB = (kk * 32 + b_kext) ^ b_xor;
#pragma unroll
            for (int mi = 0; mi < 4; mi++)
                ldm_x4(a[mi], Ab + mi * 2048 + kbA);
#pragma unroll
            for (int nt = 0; nt < 2; nt++)
                ldm_x4_t(b[nt], Bb + nt * 2048 + kbB);
#pragma unroll
            for (int mi = 0; mi < 4; mi++)
#pragma unroll
                for (int ni = 0; ni < 4; ni++)
                    mma_fp16h(hfr[mi][ni], a[mi], &b[ni >> 1][(ni & 1) * 2]);
        }
    }

    // ---- epilogue: h2 -> float, exp-sum per row -> one atomic per row ----
    __syncthreads();
    float* red = (float*)smem;
    if (tid < MT) red[tid] = 0.f;
    __syncthreads();

#pragma unroll
    for (int mi = 0; mi < 4; mi++) {
        const int rl = wm * 64 + mi * 16 + (lane >> 2);
        float s0 = 0.f, s1 = 0.f;
#pragma unroll
        for (int ni = 0; ni < 4; ni++) {
            const int cc = col0 + wn * 32 + ni * 8 + (lane & 3) * 2;
            float2 f01 = __half22float2(*(const __half2*)&hfr[mi][ni][0]);
            float2 f23 = __half22float2(*(const __half2*)&hfr[mi][ni][1]);
            if (cc < col_hi) {
                float bb = bias[cc];
                s0 += __expf(f01.x + bb - MGUARD);
                s1 += __expf(f23.x + bb - MGUARD);
            }
            if (cc + 1 < col_hi) {
                float bb = bias[cc + 1];
                s0 += __expf(f01.y + bb - MGUARD);
                s1 += __expf(f23.y + bb - MGUARD);
            }
        }
        s0 += __shfl_xor_sync(0xffffffffu, s0, 1);
        s0 += __shfl_xor_sync(0xffffffffu, s0, 2);
        s1 += __shfl_xor_sync(0xffffffffu, s1, 1);
        s1 += __shfl_xor_sync(0xffffffffu, s1, 2);
        if ((lane & 3) == 0) {
            atomicAdd(&red[rl], s0);
            atomicAdd(&red[rl + 8], s1);
        }
    }
    __syncthreads();

    if (tid < MT) {
        int rr = row0 + tid;
        if (rr < cnt) {
            int orow = rowlist ? rowlist[rr] : rr;
            atomicAdd(&acc[orow], red[tid]);
        }
    }
}

// ---------------- finalize ----------------
__global__ void __launch_bounds__(256)
finalize_kernel(const float* __restrict__ A,
                const int*   __restrict__ target,
                const float* __restrict__ W,
                const float* __restrict__ bias,
                const float* __restrict__ TV,
                const float* __restrict__ TB,
                float* __restrict__ out, int out_size)
{
    int gwarp = (blockIdx.x * blockDim.x + threadIdx.x) >> 5;
    int lane = threadIdx.x & 31;
    if (gwarp >= NROWS) return;
    int r = gwarp;
    int t = target[r];

    const float4* a4   = (const float4*)(A + (size_t)r * DIM);
    const float4* wt4  = (const float4*)(W + (size_t)t * DIM);
    const float4* tv04 = (const float4*)(TV);
    const float4* tv14 = (const float4*)(TV + DIM);

    float dwt = 0.f, d0 = 0.f, d1 = 0.f;
    for (int i = lane; i < DIM / 4; i += 32) {
        float4 a = a4[i], w = wt4[i], v0 = tv04[i], v1 = tv14[i];
        dwt += a.x * w.x  + a.y * w.y  + a.z * w.z  + a.w * w.w;
        d0  += a.x * v0.x + a.y * v0.y + a.z * v0.z + a.w * v0.w;
        d1  += a.x * v1.x + a.y * v1.y + a.z * v1.z + a.w * v1.w;
    }
#pragma unroll
    for (int o = 16; o > 0; o >>= 1) {
        dwt += __shfl_xor_sync(0xffffffffu, dwt, o);
        d0  += __shfl_xor_sync(0xffffffffu, d0,  o);
        d1  += __shfl_xor_sync(0xffffffffu, d1,  o);
    }

    if (lane == 0) {
        float tv0l = d0 + TB[0];
        float tv1l = d1 + TB[1];
        float head_sum = g_head[r] + __expf(tv0l - MGUARD) + __expf(tv1l - MGUARD);
        float head_lse = logf(head_sum) + MGUARD;

        int c = (t >= CUT0) + (t >= CUT1);
        float wt_logit = dwt + bias[t];
        float gather = (c == 0) ? wt_logit : ((c == 1) ? tv0l : tv1l);
        float head_term = gather - head_lse;

        float tail_term = 0.f;
        if (c > 0) {
            float ts = (c == 1) ? g_t1[r] : g_t2[r];
            tail_term = wt_logit - (logf(ts) + MGUARD);
        }
        float o = head_term + tail_term;
        if (r < out_size) out[r] = o;
        if (out_size > NROWS) atomicAdd(&out[NROWS], -o / (float)NROWS);
    }
}

// ---------------- launch ----------------
extern "C" void kernel_launch(void* const* d_in, const int* in_sizes, int n_in,
                              void* d_out, int out_size)
{
    const float* input  = (const float*)d_in[0];
    const int*   target = (const int*)  d_in[1];
    const float* weight = (const float*)d_in[2];
    const float* bias   = (const float*)d_in[3];
    const float* tvec   = (const float*)d_in[4];
    const float* tbias  = (const float*)d_in[5];
    float* out = (float*)d_out;

    cudaFuncSetAttribute(hmma_fused, cudaFuncAttributeMaxDynamicSharedMemorySize, SM_TOTAL);

    init_kernel<<<(NROWS + 255) / 256, 256>>>(out, out_size);
    prep_kernel<<<(int)PREP_BLOCKS, 256>>>(input, weight, target);

    {   // fused exp-sum GEMM over all regions
        dim3 grid(RT, YTOT);              // 64 x 394
        hmma_fused<<<grid, 256, SM_TOTAL>>>(bias);
    }

    finalize_kernel<<<(NROWS * 32 + 255) / 256, 256>>>(
        input, target, weight, bias, tvec, tbias, out, out_size);
}

// round 11
// speedup vs baseline: 1.0680x; 1.0680x over previous
#include <cuda_runtime.h>
#include <cuda_fp16.h>
#include <math.h>
#include <stdint.h>

#define NROWS    8192
#define DIM      1024
#define NCLASSES 50257
#define CUT0     4000
#define CUT1     20000
#define MGUARD   20.0f

#define MT  128
#define NT  128
#define BK  64
#define NCH (DIM / BK)            /* 16 k-chunks */
#define RT  (NROWS / MT)          /* 64 row tiles */
#define COLS_PAD 50688

#define YT_HEAD 32
#define YT_T1   125
#define YT_T2   237
#define YTOT    (YT_HEAD + YT_T1 + YT_T2)   /* 394 */

#define STAGE_BYTES 32768         /* A 16KB + B 16KB per stage */
#define NSTAGE 2
#define SM_TOTAL (NSTAGE * STAGE_BYTES)     /* 64KB -> 3 CTAs/SM (192KB) */

#define SW128(o) ((o) ^ (((o) >> 3) & 0x70))

/* prep kernel block partition */
#define CVTW_BLOCKS (((long)COLS_PAD * DIM / 16 + 255) / 256)   /* 12672 */
#define CVTA_BLOCKS (((long)NROWS * DIM / 16 + 255) / 256)      /* 2048 */
#define CLS_BLOCKS  (NROWS / 256)                               /* 32 */
#define PREP_BLOCKS (CVTW_BLOCKS + CVTA_BLOCKS + CLS_BLOCKS)

// ---------------- device scratch ----------------
__device__ __align__(256) __half g_A16[(size_t)NROWS * DIM];
__device__ __align__(256) __half g_W16[(size_t)COLS_PAD * DIM];
__device__ float g_head[NROWS];
__device__ float g_t1[NROWS];
__device__ float g_t2[NROWS];
__device__ int   g_rows_c1[NROWS];
__device__ int   g_rows_c2[NROWS];
__device__ int   g_cnt[2];

// ---------------- PTX helpers ----------------
__device__ __forceinline__ uint32_t smem_u32(const void* p) {
    uint32_t a;
    asm("{ .reg .u64 t; cvta.to.shared.u64 t, %1; cvt.u32.u64 %0, t; }" : "=r"(a) : "l"(p));
    return a;
}
__device__ __forceinline__ void cp16(uint32_t dst, const void* src) {
    asm volatile("cp.async.cg.shared.global [%0], [%1], 16;" :: "r"(dst), "l"(src) : "memory");
}
__device__ __forceinline__ void cp_commit() {
    asm volatile("cp.async.commit_group;" ::: "memory");
}
template <int N>
__device__ __forceinline__ void cp_wait() {
    asm volatile("cp.async.wait_group %0;" :: "n"(N) : "memory");
}
__device__ __forceinline__ void ldm_x4(uint32_t* r, uint32_t addr) {
    asm volatile("ldmatrix.sync.aligned.m8n8.x4.shared.b16 {%0,%1,%2,%3}, [%4];"
                 : "=r"(r[0]), "=r"(r[1]), "=r"(r[2]), "=r"(r[3]) : "r"(addr));
}
__device__ __forceinline__ void ldm_x4_t(uint32_t* r, uint32_t addr) {
    asm volatile("ldmatrix.sync.aligned.m8n8.x4.trans.shared.b16 {%0,%1,%2,%3}, [%4];"
                 : "=r"(r[0]), "=r"(r[1]), "=r"(r[2]), "=r"(r[3]) : "r"(addr));
}
// fp16-accumulate HMMA (element positions match f32 variant's c0..c3)
__device__ __forceinline__ void mma_fp16h(uint32_t* c, const uint32_t* a, const uint32_t* b) {
    asm volatile(
        "mma.sync.aligned.m16n8k16.row.col.f16.f16.f16.f16 "
        "{%0,%1}, {%2,%3,%4,%5}, {%6,%7}, {%0,%1};"
        : "+r"(c[0]), "+r"(c[1])
        : "r"(a[0]), "r"(a[1]), "r"(a[2]), "r"(a[3]), "r"(b[0]), "r"(b[1]));
}

// ---------------- init ----------------
__global__ void init_kernel(float* out, int out_size) {
    int i = blockIdx.x * blockDim.x + threadIdx.x;
    if (i < NROWS) { g_head[i] = 0.f; g_t1[i] = 0.f; g_t2[i] = 0.f; }
    if (i < 2) g_cnt[i] = 0;
    if (i == 0 && out_size > NROWS) out[NROWS] = 0.f;
}

// ---------------- prep: weight-cvt + input-cvt + classify ----------------
__device__ __forceinline__ uint32_t pack2hf(float a, float b) {
    __half2 t = __floats2half2_rn(a, b);
    return *reinterpret_cast<uint32_t*>(&t);
}
__device__ __forceinline__ void cvt16(const float* __restrict__ src, __half* __restrict__ dst,
                                      long i, long n_src) {
    uint4 o;
    if (i < n_src) {
        float4 v0 = ((const float4*)src)[i / 4];
        float4 v1 = ((const float4*)src)[i / 4 + 1];
        float4 v2 = ((const float4*)src)[i / 4 + 2];
        float4 v3 = ((const float4*)src)[i / 4 + 3];
        uint4 p;
        p.x = pack2hf(v0.x, v0.y); p.y = pack2hf(v0.z, v0.w);
        p.z = pack2hf(v1.x, v1.y); p.w = pack2hf(v1.z, v1.w);
        o = p;
        *((uint4*)(dst + i)) = o;
        p.x = pack2hf(v2.x, v2.y); p.y = pack2hf(v2.z, v2.w);
        p.z = pack2hf(v3.x, v3.y); p.w = pack2hf(v3.z, v3.w);
        *((uint4*)(dst + i + 8)) = p;
    } else {
        o = make_uint4(0, 0, 0, 0);
        *((uint4*)(dst + i)) = o;
        *((uint4*)(dst + i + 8)) = o;
    }
}
__global__ void prep_kernel(const float* __restrict__ input,
                            const float* __restrict__ weight,
                            const int*   __restrict__ target) {
    long bx = blockIdx.x;
    if (bx < CVTW_BLOCKS) {
        long i = (bx * 256 + threadIdx.x) * 16;
        if (i < (long)COLS_PAD * DIM)
            cvt16(weight, g_W16, i, (long)NCLASSES * DIM);
    } else if (bx < CVTW_BLOCKS + CVTA_BLOCKS) {
        long i = ((bx - CVTW_BLOCKS) * 256 + threadIdx.x) * 16;
        if (i < (long)NROWS * DIM)
            cvt16(input, g_A16, i, (long)NROWS * DIM);
    } else {
        int r = (int)(bx - CVTW_BLOCKS - CVTA_BLOCKS) * 256 + threadIdx.x;
        if (r < NROWS) {
            int t = target[r];
            if (t >= CUT1)      { int p = atomicAdd(&g_cnt[1], 1); g_rows_c2[p] = r; }
            else if (t >= CUT0) { int p = atomicAdd(&g_cnt[0], 1); g_rows_c1[p] = r; }
        }
    }
}

// ---------------- fused HMMA exp-sum GEMM ----------------
// 128x128 CTA, 256 threads (2 M-warps x 4 N-warps, warp 64x32), BK=64,
// 2-stage cp.async, fp16 accumulators, compact addressing, 3 CTAs/SM.
__global__ void __launch_bounds__(256, 3)
hmma_fused(const float* __restrict__ bias)
{
    extern __shared__ char smem[];
    const uint32_t sb = smem_u32(smem);
    const int tid = threadIdx.x;
    const int wid = tid >> 5;
    const int lane = tid & 31;

    // ---- region decode ----
    int ty = blockIdx.y;
    int col_lo, col_hi;
    const int* rowlist;
    int cnt;
    float* acc;
    if (ty < YT_HEAD) {
        col_lo = 0; col_hi = CUT0; rowlist = nullptr; cnt = NROWS; acc = g_head;
    } else if (ty < YT_HEAD + YT_T1) {
        ty -= YT_HEAD;
        col_lo = CUT0; col_hi = CUT1; rowlist = g_rows_c1; cnt = g_cnt[0]; acc = g_t1;
    } else {
        ty -= YT_HEAD + YT_T1;
        col_lo = CUT1; col_hi = NCLASSES; rowlist = g_rows_c2; cnt = g_cnt[1]; acc = g_t2;
    }
    const int row0 = blockIdx.x * MT;
    if (row0 >= cnt) return;
    const int col0 = col_lo + ty * NT;

    // ---- compact cp.async setup ----
    // per-thread: 4 A chunks (rows r_a+64i) + 4 B chunks (rows r_a+32i), 16B each
    const int r_a = tid >> 3;            // 0..31 base smem row
    const int kc  = tid & 7;             // 16B unit within 128B row
    int arow_idx[4];                     // gathered global A rows (ints, not ptrs)
#pragma unroll
    for (int i = 0; i < 4; i++) {
        int rr = row0 + (tid >> 3) + 32 * i;
        if (rowlist) arow_idx[i] = rowlist[rr < cnt ? rr : cnt - 1];
        else         arow_idx[i] = rr;
    }
    const __half* bsrc0 = g_W16 + (size_t)(col0 + r_a) * DIM + kc * 8;
    const uint32_t adst0 = sb + SW128(r_a * 128 + kc * 16);          // +4096/i
    const uint32_t bdst0 = sb + 16384 + SW128(r_a * 128 + kc * 16);  // +4096/i

    // prologue: stages 0,1
#pragma unroll
    for (int s = 0; s < 2; s++) {
        const uint32_t st = s * STAGE_BYTES;
        const int kof = s * BK;
#pragma unroll
        for (int i = 0; i < 4; i++) {
            cp16(adst0 + 4096 * i + st, g_A16 + (size_t)arow_idx[i] * DIM + kc * 8 + kof);
            cp16(bdst0 + 4096 * i + st, bsrc0 + (size_t)32 * DIM * i + kof);
        }
        cp_commit();
    }

    // ---- warp fragment addressing ----
    const int wm = wid & 1;
    const int wn = wid >> 1;
    const int arow = wm * 64 + (lane & 15);
    const uint32_t a_xor = (arow & 7) << 4;
    const uint32_t a_kext = (lane >> 4) << 4;
    const int ln = lane & 7, sel = lane >> 3;
    const int brow = wn * 32 + ln + ((sel >> 1) << 3);
    const uint32_t b_xor = (uint32_t)ln << 4;
    const uint32_t b_kext = (sel & 1) << 4;

    uint32_t hfr[4][4][2];
#pragma unroll
    for (int mi = 0; mi < 4; mi++)
#pragma unroll
        for (int ni = 0; ni < 4; ni++) { hfr[mi][ni][0] = 0u; hfr[mi][ni][1] = 0u; }

    for (int ch = 0; ch < NCH; ch++) {
        if (ch < NCH - 1) cp_wait<1>(); else cp_wait<0>();
        __syncthreads();

        const uint32_t st = (ch & 1) * STAGE_BYTES;
        const uint32_t Ab = sb + st + (uint32_t)arow * 128;
        const uint32_t Bb = sb + st + 16384 + (uint32_t)brow * 128;

#pragma unroll
        for (int kk = 0; kk < 4; kk++) {
            uint32_t a[4][4], b[2][4];
            const uint32_t kbA = (kk * 32 + a_kext) ^ a_xor;
            const uint32_t kbB = (kk * 32 + b_kext) ^ b_xor;
#pragma unroll
            for (int mi = 0; mi < 4; mi++)
                ldm_x4(a[mi], Ab + mi * 2048 + kbA);
#pragma unroll
            for (int nt = 0; nt < 2; nt++)
                ldm_x4_t(b[nt], Bb + nt * 2048 + kbB);
#pragma unroll
            for (int mi = 0; mi < 4; mi++)
#pragma unroll
                for (int ni = 0; ni < 4; ni++)
                    mma_fp16h(hfr[mi][ni], a[mi], &b[ni >> 1][(ni & 1) * 2]);
        }
        __syncthreads();

        if (ch + 2 < NCH) {
            const int kof = (ch + 2) * BK;
#pragma unroll
            for (int i = 0; i < 4; i++) {
                cp16(adst0 + 4096 * i + st, g_A16 + (size_t)arow_idx[i] * DIM + kc * 8 + kof);
                cp16(bdst0 + 4096 * i + st, bsrc0 + (size_t)32 * DIM * i + kof);
            }
            cp_commit();
        }
    }

    // ---- epilogue: h2 -> float, exp-sum per row -> one atomic per row ----
    float* red = (float*)smem;
    if (tid < MT) red[tid] = 0.f;
    __syncthreads();

#pragma unroll
    for (int mi = 0; mi < 4; mi++) {
        const int rl = wm * 64 + mi * 16 + (lane >> 2);
        float s0 = 0.f, s1 = 0.f;
#pragma unroll
        for (int ni = 0; ni < 4; ni++) {
            const int cc = col0 + wn * 32 + ni * 8 + (lane & 3) * 2;
            float2 f01 = __half22float2(*(const __half2*)&hfr[mi][ni][0]);
            float2 f23 = __half22float2(*(const __half2*)&hfr[mi][ni][1]);
            if (cc < col_hi) {
                float bb = bias[cc];
                s0 += __expf(f01.x + bb - MGUARD);
                s1 += __expf(f23.x + bb - MGUARD);
            }
            if (cc + 1 < col_hi) {
                float bb = bias[cc + 1];
                s0 += __expf(f01.y + bb - MGUARD);
                s1 += __expf(f23.y + bb - MGUARD);
            }
        }
        s0 += __shfl_xor_sync(0xffffffffu, s0, 1);
        s0 += __shfl_xor_sync(0xffffffffu, s0, 2);
        s1 += __shfl_xor_sync(0xffffffffu, s1, 1);
        s1 += __shfl_xor_sync(0xffffffffu, s1, 2);
        if ((lane & 3) == 0) {
            atomicAdd(&red[rl], s0);
            atomicAdd(&red[rl + 8], s1);
        }
    }
    __syncthreads();

    if (tid < MT) {
        int rr = row0 + tid;
        if (rr < cnt) {
            int orow = rowlist ? rowlist[rr] : rr;
            atomicAdd(&acc[orow], red[tid]);
        }
    }
}

// ---------------- finalize ----------------
__global__ void __launch_bounds__(256)
finalize_kernel(const float* __restrict__ A,
                const int*   __restrict__ target,
                const float* __restrict__ W,
                const float* __restrict__ bias,
                const float* __restrict__ TV,
                const float* __restrict__ TB,
                float* __restrict__ out, int out_size)
{
    int gwarp = (blockIdx.x * blockDim.x + threadIdx.x) >> 5;
    int lane = threadIdx.x & 31;
    if (gwarp >= NROWS) return;
    int r = gwarp;
    int t = target[r];

    const float4* a4   = (const float4*)(A + (size_t)r * DIM);
    const float4* wt4  = (const float4*)(W + (size_t)t * DIM);
    const float4* tv04 = (const float4*)(TV);
    const float4* tv14 = (const float4*)(TV + DIM);

    float dwt = 0.f, d0 = 0.f, d1 = 0.f;
    for (int i = lane; i < DIM / 4; i += 32) {
        float4 a = a4[i], w = wt4[i], v0 = tv04[i], v1 = tv14[i];
        dwt += a.x * w.x  + a.y * w.y  + a.z * w.z  + a.w * w.w;
        d0  += a.x * v0.x + a.y * v0.y + a.z * v0.z + a.w * v0.w;
        d1  += a.x * v1.x + a.y * v1.y + a.z * v1.z + a.w * v1.w;
    }
#pragma unroll
    for (int o = 16; o > 0; o >>= 1) {
        dwt += __shfl_xor_sync(0xffffffffu, dwt, o);
        d0  += __shfl_xor_sync(0xffffffffu, d0,  o);
        d1  += __shfl_xor_sync(0xffffffffu, d1,  o);
    }

    if (lane == 0) {
        float tv0l = d0 + TB[0];
        float tv1l = d1 + TB[1];
        float head_sum = g_head[r] + __expf(tv0l - MGUARD) + __expf(tv1l - MGUARD);
        float head_lse = logf(head_sum) + MGUARD;

        int c = (t >= CUT0) + (t >= CUT1);
        float wt_logit = dwt + bias[t];
        float gather = (c == 0) ? wt_logit : ((c == 1) ? tv0l : tv1l);
        float head_term = gather - head_lse;

        float tail_term = 0.f;
        if (c > 0) {
            float ts = (c == 1) ? g_t1[r] : g_t2[r];
            tail_term = wt_logit - (logf(ts) + MGUARD);
        }
        float o = head_term + tail_term;
        if (r < out_size) out[r] = o;
        if (out_size > NROWS) atomicAdd(&out[NROWS], -o / (float)NROWS);
    }
}

// ---------------- launch ----------------
extern "C" void kernel_launch(void* const* d_in, const int* in_sizes, int n_in,
                              void* d_out, int out_size)
{
    const float* input  = (const float*)d_in[0];
    const int*   target = (const int*)  d_in[1];
    const float* weight = (const float*)d_in[2];
    const float* bias   = (const float*)d_in[3];
    const float* tvec   = (const float*)d_in[4];
    const float* tbias  = (const float*)d_in[5];
    float* out = (float*)d_out;

    cudaFuncSetAttribute(hmma_fused, cudaFuncAttributeMaxDynamicSharedMemorySize, SM_TOTAL);

    init_kernel<<<(NROWS + 255) / 256, 256>>>(out, out_size);
    prep_kernel<<<(int)PREP_BLOCKS, 256>>>(input, weight, target);

    {   // fused exp-sum GEMM over all regions
        dim3 grid(RT, YTOT);              // 64 x 394
        hmma_fused<<<grid, 256, SM_TOTAL>>>(bias);
    }

    finalize_kernel<<<(NROWS * 32 + 255) / 256, 256>>>(
        input, target, weight, bias, tvec, tbias, out, out_size);
}